// round 2
// baseline (speedup 1.0000x reference)
#include <cuda_runtime.h>

// CircleProjectionLayer: out = center + (x - center) * min(1, R / max(||x-center||, 1e-12))
// R = 1.0, B = 8388608 points, AoS float32 [B,3].
//
// Memory-bound: 302 MB total traffic. Strategy: 4 points (= 3 float4) per thread
// so every global access is a 16B vector load/store; a warp's three LDG.128
// jointly cover a contiguous 1536B region (all sectors consumed via L1).

#define RADIUS_F 1.0f

__global__ __launch_bounds__(256)
void circle_proj_kernel(const float4* __restrict__ x4,
                        const float4* __restrict__ c4,
                        float4* __restrict__ o4,
                        int n_groups)   // n_groups = B/4 ; each group = 3 float4
{
    int i = blockIdx.x * blockDim.x + threadIdx.x;
    if (i >= n_groups) return;

    long base = 3L * i;

    float4 xa = x4[base + 0];
    float4 xb = x4[base + 1];
    float4 xc = x4[base + 2];
    float4 ca = c4[base + 0];
    float4 cb = c4[base + 1];
    float4 cc = c4[base + 2];

    // Unpack 12 floats -> 4 points (p, q) and compute per-point projection.
    float xv[12] = {xa.x, xa.y, xa.z, xa.w, xb.x, xb.y, xb.z, xb.w, xc.x, xc.y, xc.z, xc.w};
    float cv[12] = {ca.x, ca.y, ca.z, ca.w, cb.x, cb.y, cb.z, cb.w, cc.x, cc.y, cc.z, cc.w};
    float ov[12];

    #pragma unroll
    for (int p = 0; p < 4; ++p) {
        float dx = xv[3*p + 0] - cv[3*p + 0];
        float dy = xv[3*p + 1] - cv[3*p + 1];
        float dz = xv[3*p + 2] - cv[3*p + 2];
        float n2 = fmaf(dx, dx, fmaf(dy, dy, dz * dz));
        // scale = min(1, R / max(n, 1e-12))  ==  min(1, R * rsqrt(max(n2, 1e-24)))
        float s = fminf(1.0f, RADIUS_F * rsqrtf(fmaxf(n2, 1e-24f)));
        ov[3*p + 0] = fmaf(dx, s, cv[3*p + 0]);
        ov[3*p + 1] = fmaf(dy, s, cv[3*p + 1]);
        ov[3*p + 2] = fmaf(dz, s, cv[3*p + 2]);
    }

    o4[base + 0] = make_float4(ov[0], ov[1], ov[2],  ov[3]);
    o4[base + 1] = make_float4(ov[4], ov[5], ov[6],  ov[7]);
    o4[base + 2] = make_float4(ov[8], ov[9], ov[10], ov[11]);
}

// Scalar tail kernel for any leftover points (B not divisible by 4). For the
// benched shape (B = 8388608) this launches 0 blocks, but keep it general.
__global__ void circle_proj_tail(const float* __restrict__ x,
                                 const float* __restrict__ c,
                                 float* __restrict__ o,
                                 int start_pt, int n_pt)
{
    int p = start_pt + blockIdx.x * blockDim.x + threadIdx.x;
    if (p >= n_pt) return;
    float dx = x[3*p + 0] - c[3*p + 0];
    float dy = x[3*p + 1] - c[3*p + 1];
    float dz = x[3*p + 2] - c[3*p + 2];
    float n2 = fmaf(dx, dx, fmaf(dy, dy, dz * dz));
    float s = fminf(1.0f, RADIUS_F * rsqrtf(fmaxf(n2, 1e-24f)));
    o[3*p + 0] = fmaf(dx, s, c[3*p + 0]);
    o[3*p + 1] = fmaf(dy, s, c[3*p + 1]);
    o[3*p + 2] = fmaf(dz, s, c[3*p + 2]);
}

extern "C" void kernel_launch(void* const* d_in, const int* in_sizes, int n_in,
                              void* d_out, int out_size)
{
    const float* x = (const float*)d_in[0];
    const float* c = (const float*)d_in[1];
    float* o = (float*)d_out;

    int total_floats = in_sizes[0];      // B * 3
    int n_pts = total_floats / 3;
    int n_groups = n_pts / 4;            // 4 points per thread

    if (n_groups > 0) {
        int threads = 256;
        int blocks = (n_groups + threads - 1) / threads;
        circle_proj_kernel<<<blocks, threads>>>(
            (const float4*)x, (const float4*)c, (float4*)o, n_groups);
    }

    int done_pts = n_groups * 4;
    int rem = n_pts - done_pts;
    if (rem > 0) {
        circle_proj_tail<<<(rem + 255) / 256, 256>>>(x, c, o, done_pts, n_pts);
    }
}